// round 1
// baseline (speedup 1.0000x reference)
#include <cuda_runtime.h>
#include <cstdint>

// ============================================================================
// CrossAttentionFuse: B=4, Nq=Nk=2048, q/kv/out dim=1024, H=16, hd=64
//   q = Qtok@Wq ; k = (Ktok@Wk)*wK[:,None] ; v = Vtok@Wv   (head-major)
//   att = softmax(q k^T / 8) v    (no-max softmax: logits are small)
//   out = att@Wo + bo
// All tensor math in tf32 mma.sync with fp32 accumulation.
// ============================================================================

#define M_TOT 8192        // B*N
#define DIM   1024

// Static scratch (allocation-free rule): 4 x 32MB fp32
__device__ float g_q[M_TOT * DIM];
__device__ float g_k[M_TOT * DIM];
__device__ float g_v[M_TOT * DIM];
__device__ float g_att[M_TOT * DIM];

__device__ __forceinline__ unsigned f2tf(float x) {
    unsigned u;
    asm("cvt.rna.tf32.f32 %0, %1;\n" : "=r"(u) : "f"(x));
    return u;
}

__device__ __forceinline__ uint4 f2tf4(float4 v) {
    uint4 u;
    u.x = f2tf(v.x); u.y = f2tf(v.y); u.z = f2tf(v.z); u.w = f2tf(v.w);
    return u;
}

__device__ __forceinline__ void mma8(float c[4], const unsigned a[4],
                                     unsigned b0, unsigned b1) {
    asm volatile(
        "mma.sync.aligned.m16n8k8.row.col.f32.tf32.tf32.f32 "
        "{%0,%1,%2,%3}, {%4,%5,%6,%7}, {%8,%9}, {%0,%1,%2,%3};\n"
        : "+f"(c[0]), "+f"(c[1]), "+f"(c[2]), "+f"(c[3])
        : "r"(a[0]), "r"(a[1]), "r"(a[2]), "r"(a[3]), "r"(b0), "r"(b1));
}

// ============================================================================
// Generic GEMM: C[M=8192, N=1024] = A[8192,1024] @ W[1024,1024]
// mode 0: write head-major  out[((b*16+h)*2048+n)*64+d]
// mode 1: mode 0, scaled per-row by wK[row]   (K projection)
// mode 2: write row-major + bias              (output projection)
// CTA tile 128x128, kk=32, 8 warps in 4(M)x2(N), warp tile 32x64.
// ============================================================================
__global__ __launch_bounds__(256) void gemm_tf32(
    const float* __restrict__ A, const float* __restrict__ W,
    float* __restrict__ out, const float* __restrict__ wK,
    const float* __restrict__ bias, int mode)
{
    __shared__ unsigned As[128][36];   // pitch 36: a-frag banks (4g+tig) distinct
    __shared__ unsigned Ws[32][136];   // pitch 136: b-frag banks (8*tig+g) distinct

    const int tid  = threadIdx.x;
    const int warp = tid >> 5, lane = tid & 31;
    const int g    = lane >> 2, tig = lane & 3;
    const int wm   = warp >> 1, wn = warp & 1;
    const int m0   = blockIdx.y * 128, n0 = blockIdx.x * 128;

    float acc[2][8][4];
    #pragma unroll
    for (int i = 0; i < 2; i++)
        #pragma unroll
        for (int j = 0; j < 8; j++)
            #pragma unroll
            for (int e = 0; e < 4; e++) acc[i][j][e] = 0.f;

    for (int kt = 0; kt < DIM; kt += 32) {
        // stage A 128x32 (pre-converted to tf32)
        #pragma unroll
        for (int i = 0; i < 4; i++) {
            int idx = tid + i * 256;                 // 0..1023
            int r = idx >> 3, c4 = (idx & 7) * 4;
            float4 v = *reinterpret_cast<const float4*>(
                A + (size_t)(m0 + r) * DIM + kt + c4);
            *reinterpret_cast<uint4*>(&As[r][c4]) = f2tf4(v);
        }
        // stage W 32x128
        #pragma unroll
        for (int i = 0; i < 4; i++) {
            int idx = tid + i * 256;
            int r = idx >> 5, c4 = (idx & 31) * 4;
            float4 v = *reinterpret_cast<const float4*>(
                W + (size_t)(kt + r) * DIM + n0 + c4);
            *reinterpret_cast<uint4*>(&Ws[r][c4]) = f2tf4(v);
        }
        __syncthreads();

        #pragma unroll
        for (int ks = 0; ks < 4; ks++) {
            const int k8 = ks * 8;
            unsigned a[2][4];
            #pragma unroll
            for (int mt = 0; mt < 2; mt++) {
                int rb = wm * 32 + mt * 16;
                a[mt][0] = As[rb + g    ][k8 + tig];
                a[mt][1] = As[rb + g + 8][k8 + tig];
                a[mt][2] = As[rb + g    ][k8 + tig + 4];
                a[mt][3] = As[rb + g + 8][k8 + tig + 4];
            }
            #pragma unroll
            for (int nt = 0; nt < 8; nt++) {
                int cb = wn * 64 + nt * 8;
                unsigned b0 = Ws[k8 + tig    ][cb + g];
                unsigned b1 = Ws[k8 + tig + 4][cb + g];
                mma8(acc[0][nt], a[0], b0, b1);
                mma8(acc[1][nt], a[1], b0, b1);
            }
        }
        __syncthreads();
    }

    // epilogue
    #pragma unroll
    for (int mt = 0; mt < 2; mt++) {
        #pragma unroll
        for (int nt = 0; nt < 8; nt++) {
            int row = m0 + wm * 32 + mt * 16 + g;
            int col = n0 + wn * 64 + nt * 8 + 2 * tig;
            float v0 = acc[mt][nt][0], v1 = acc[mt][nt][1];
            float v2 = acc[mt][nt][2], v3 = acc[mt][nt][3];
            if (mode == 2) {
                float b0v = bias[col], b1v = bias[col + 1];
                *reinterpret_cast<float2*>(out + (size_t)row * DIM + col) =
                    make_float2(v0 + b0v, v1 + b1v);
                *reinterpret_cast<float2*>(out + (size_t)(row + 8) * DIM + col) =
                    make_float2(v2 + b0v, v3 + b1v);
            } else {
                if (mode == 1) {
                    float w0 = wK[row], w1 = wK[row + 8];
                    v0 *= w0; v1 *= w0; v2 *= w1; v3 *= w1;
                }
                size_t b = (size_t)(row >> 11);       // row / 2048
                size_t n = (size_t)(row & 2047);
                size_t h = (size_t)(col >> 6);
                size_t d = (size_t)(col & 63);
                size_t base = ((b * 16 + h) * 2048 + n) * 64 + d;
                *reinterpret_cast<float2*>(out + base) = make_float2(v0, v1);
                *reinterpret_cast<float2*>(out + base + 8 * 64) = make_float2(v2, v3);
            }
        }
    }
}

// ============================================================================
// Attention: one CTA = one (b,h) x 64-query tile. 256 threads (8 warps 4x2).
// No-max softmax: O = (sum_k exp(s_k) v_k) / (sum_k exp(s_k)).
// Q fragments live in registers (scaled by 1/8, tf32).
// K tile and P share one smem buffer (KP); V separate. All tf32-in-smem.
// ============================================================================
__global__ __launch_bounds__(256) void attn_tf32(
    const float* __restrict__ qbuf, const float* __restrict__ kbuf,
    const float* __restrict__ vbuf, float* __restrict__ attout)
{
    __shared__ unsigned KP[64][68];   // pitch 68 (==4 mod 32): conflict-free frags
    __shared__ unsigned Vt[64][72];   // pitch 72 (==8 mod 32): conflict-free b-frags
    __shared__ float    den2[64][2];

    const int tid  = threadIdx.x;
    const int warp = tid >> 5, lane = tid & 31;
    const int g    = lane >> 2, tig = lane & 3;
    const int wm   = warp >> 1, wn = warp & 1;
    const int bh   = blockIdx.y;                 // 0..63
    const int q0   = blockIdx.x * 64;
    const int b    = bh >> 4, h = bh & 15;
    const size_t qbase  = ((size_t)bh * 2048 + q0) * 64;
    const size_t kvbase = (size_t)bh * 2048 * 64;
    const int rb = wm * 16;

    // Q fragments (scale 1/sqrt(64)=0.125 folded in), resident all kernel
    unsigned qf[8][4];
    #pragma unroll
    for (int ks = 0; ks < 8; ks++) {
        int c = ks * 8 + tig;
        qf[ks][0] = f2tf(qbuf[qbase + (size_t)(rb + g    ) * 64 + c    ] * 0.125f);
        qf[ks][1] = f2tf(qbuf[qbase + (size_t)(rb + g + 8) * 64 + c    ] * 0.125f);
        qf[ks][2] = f2tf(qbuf[qbase + (size_t)(rb + g    ) * 64 + c + 4] * 0.125f);
        qf[ks][3] = f2tf(qbuf[qbase + (size_t)(rb + g + 8) * 64 + c + 4] * 0.125f);
    }

    float oacc[4][4];
    #pragma unroll
    for (int nt = 0; nt < 4; nt++)
        #pragma unroll
        for (int e = 0; e < 4; e++) oacc[nt][e] = 0.f;
    float dsum0 = 0.f, dsum1 = 0.f;   // per-thread denominator partials

    for (int kt = 0; kt < 32; kt++) {
        // stage K,V tiles (64 keys x 64 dims) as tf32
        size_t src = kvbase + (size_t)kt * 64 * 64;
        #pragma unroll
        for (int i = 0; i < 4; i++) {
            int idx = tid + i * 256;               // 0..1023
            int r = idx >> 4, c4 = (idx & 15) * 4;
            float4 kv = *reinterpret_cast<const float4*>(kbuf + src + (size_t)r * 64 + c4);
            *reinterpret_cast<uint4*>(&KP[r][c4]) = f2tf4(kv);
            float4 vv = *reinterpret_cast<const float4*>(vbuf + src + (size_t)r * 64 + c4);
            *reinterpret_cast<uint4*>(&Vt[r][c4]) = f2tf4(vv);
        }
        __syncthreads();

        // S = Q K^T  (M=64 q, N=64 keys, K=64 dims)
        float sacc[4][4];
        #pragma unroll
        for (int nt = 0; nt < 4; nt++)
            #pragma unroll
            for (int e = 0; e < 4; e++) sacc[nt][e] = 0.f;
        #pragma unroll
        for (int ks = 0; ks < 8; ks++) {
            const int k8 = ks * 8;
            #pragma unroll
            for (int nt = 0; nt < 4; nt++) {
                int key = wn * 32 + nt * 8 + g;
                unsigned b0 = KP[key][k8 + tig];
                unsigned b1 = KP[key][k8 + tig + 4];
                mma8(sacc[nt], qf[ks], b0, b1);
            }
        }
        __syncthreads();   // everyone done reading K before P overwrites it

        // P = exp(S) -> smem (tf32); accumulate denominator in registers
        #pragma unroll
        for (int nt = 0; nt < 4; nt++) {
            int colb = wn * 32 + nt * 8 + 2 * tig;
            unsigned u0 = f2tf(__expf(sacc[nt][0]));
            unsigned u1 = f2tf(__expf(sacc[nt][1]));
            unsigned u2 = f2tf(__expf(sacc[nt][2]));
            unsigned u3 = f2tf(__expf(sacc[nt][3]));
            KP[rb + g    ][colb    ] = u0;
            KP[rb + g    ][colb + 1] = u1;
            KP[rb + g + 8][colb    ] = u2;
            KP[rb + g + 8][colb + 1] = u3;
            dsum0 += __uint_as_float(u0) + __uint_as_float(u1);
            dsum1 += __uint_as_float(u2) + __uint_as_float(u3);
        }
        __syncthreads();   // P visible

        // O += P V   (M=64 q, N=64 dims, K=64 keys)
        #pragma unroll
        for (int ks = 0; ks < 8; ks++) {
            const int k8 = ks * 8;
            unsigned a[4];
            a[0] = KP[rb + g    ][k8 + tig];
            a[1] = KP[rb + g + 8][k8 + tig];
            a[2] = KP[rb + g    ][k8 + tig + 4];
            a[3] = KP[rb + g + 8][k8 + tig + 4];
            #pragma unroll
            for (int nt = 0; nt < 4; nt++) {
                int dcol = wn * 32 + nt * 8 + g;
                unsigned b0 = Vt[k8 + tig    ][dcol];
                unsigned b1 = Vt[k8 + tig + 4][dcol];
                mma8(oacc[nt], a, b0, b1);
            }
        }
        __syncthreads();   // done with KP/Vt before next tile load
    }

    // deterministic denominator reduce: quad shuffle, then across wn via smem
    dsum0 += __shfl_xor_sync(0xffffffffu, dsum0, 1);
    dsum0 += __shfl_xor_sync(0xffffffffu, dsum0, 2);
    dsum1 += __shfl_xor_sync(0xffffffffu, dsum1, 1);
    dsum1 += __shfl_xor_sync(0xffffffffu, dsum1, 2);
    if (tig == 0) {
        den2[rb + g    ][wn] = dsum0;
        den2[rb + g + 8][wn] = dsum1;
    }
    __syncthreads();
    float inv0 = 1.f / (den2[rb + g    ][0] + den2[rb + g    ][1]);
    float inv1 = 1.f / (den2[rb + g + 8][0] + den2[rb + g + 8][1]);

    // write token-major attention output: att[b][q][h*64+d]
    #pragma unroll
    for (int nt = 0; nt < 4; nt++) {
        int row = q0 + rb + g;
        int col = h * 64 + wn * 32 + nt * 8 + 2 * tig;
        size_t base = ((size_t)b * 2048 + row) * 1024 + col;
        *reinterpret_cast<float2*>(attout + base) =
            make_float2(oacc[nt][0] * inv0, oacc[nt][1] * inv0);
        *reinterpret_cast<float2*>(attout + base + 8 * 1024) =
            make_float2(oacc[nt][2] * inv1, oacc[nt][3] * inv1);
    }
}

// ============================================================================
extern "C" void kernel_launch(void* const* d_in, const int* in_sizes, int n_in,
                              void* d_out, int out_size) {
    (void)in_sizes; (void)n_in; (void)out_size;
    const float* Qtok = (const float*)d_in[0];
    const float* Ktok = (const float*)d_in[1];
    const float* Vtok = (const float*)d_in[2];
    const float* wK   = (const float*)d_in[3];
    const float* Wq   = (const float*)d_in[4];
    const float* Wk   = (const float*)d_in[5];
    const float* Wv   = (const float*)d_in[6];
    const float* Wo   = (const float*)d_in[7];
    const float* bo   = (const float*)d_in[8];
    float* out = (float*)d_out;

    float *qb, *kb, *vb, *ab;
    cudaGetSymbolAddress((void**)&qb, g_q);
    cudaGetSymbolAddress((void**)&kb, g_k);
    cudaGetSymbolAddress((void**)&vb, g_v);
    cudaGetSymbolAddress((void**)&ab, g_att);

    dim3 gg(DIM / 128, M_TOT / 128);   // (8, 64)
    gemm_tf32<<<gg, 256>>>(Qtok, Wq, qb, nullptr, nullptr, 0);
    gemm_tf32<<<gg, 256>>>(Ktok, Wk, kb, wK,      nullptr, 1);
    gemm_tf32<<<gg, 256>>>(Vtok, Wv, vb, nullptr, nullptr, 0);
    attn_tf32<<<dim3(2048 / 64, 64), 256>>>(qb, kb, vb, ab);
    gemm_tf32<<<gg, 256>>>(ab, Wo, out, nullptr, bo, 2);
}

// round 4
// speedup vs baseline: 1.1583x; 1.1583x over previous
#include <cuda_runtime.h>
#include <cstdint>

// ============================================================================
// CrossAttentionFuse: B=4, Nq=Nk=2048, q/kv/out dim=1024, H=16, hd=64
//   q = Qtok@Wq ; k = (Ktok@Wk)*wK[:,None] ; v = Vtok@Wv   (head-major)
//   att = softmax(q k^T / 8) v    (no-max softmax: logits are small)
//   out = att@Wo + bo
// All tensor math in tf32 mma.sync with fp32 accumulation.
// ============================================================================

#define M_TOT 8192        // B*N
#define DIM   1024

// Static scratch (allocation-free rule): 4 x 32MB fp32
__device__ float g_q[M_TOT * DIM];
__device__ float g_k[M_TOT * DIM];
__device__ float g_v[M_TOT * DIM];
__device__ float g_att[M_TOT * DIM];

__device__ __forceinline__ unsigned f2tf(float x) {
    unsigned u;
    asm("cvt.rna.tf32.f32 %0, %1;\n" : "=r"(u) : "f"(x));
    return u;
}

__device__ __forceinline__ uint4 f2tf4(float4 v) {
    uint4 u;
    u.x = f2tf(v.x); u.y = f2tf(v.y); u.z = f2tf(v.z); u.w = f2tf(v.w);
    return u;
}

__device__ __forceinline__ void mma8(float c[4], const unsigned a[4],
                                     unsigned b0, unsigned b1) {
    asm volatile(
        "mma.sync.aligned.m16n8k8.row.col.f32.tf32.tf32.f32 "
        "{%0,%1,%2,%3}, {%4,%5,%6,%7}, {%8,%9}, {%0,%1,%2,%3};\n"
        : "+f"(c[0]), "+f"(c[1]), "+f"(c[2]), "+f"(c[3])
        : "r"(a[0]), "r"(a[1]), "r"(a[2]), "r"(a[3]), "r"(b0), "r"(b1));
}

// ============================================================================
// Generic GEMM: C[M=8192, N=1024] = A[8192,1024] @ W[1024,1024]
// mode 0: write head-major  out[((b*16+h)*2048+n)*64+d]
// mode 1: mode 0, scaled per-row by wK[row]   (K projection)
// mode 2: write row-major + bias              (output projection)
// CTA tile 128x128, kk=32, 8 warps in 4(M)x2(N), warp tile 32x64.
// ============================================================================
__global__ __launch_bounds__(256) void gemm_tf32(
    const float* __restrict__ A, const float* __restrict__ W,
    float* __restrict__ out, const float* __restrict__ wK,
    const float* __restrict__ bias, int mode)
{
    __shared__ unsigned As[128][36];   // pitch 36: a-frag banks (4g+tig) distinct
    __shared__ unsigned Ws[32][136];   // pitch 136: b-frag banks (8*tig+g) distinct

    const int tid  = threadIdx.x;
    const int warp = tid >> 5, lane = tid & 31;
    const int g    = lane >> 2, tig = lane & 3;
    const int wm   = warp >> 1, wn = warp & 1;
    const int m0   = blockIdx.y * 128, n0 = blockIdx.x * 128;

    float acc[2][8][4];
    #pragma unroll
    for (int i = 0; i < 2; i++)
        #pragma unroll
        for (int j = 0; j < 8; j++)
            #pragma unroll
            for (int e = 0; e < 4; e++) acc[i][j][e] = 0.f;

    for (int kt = 0; kt < DIM; kt += 32) {
        // stage A 128x32 (pre-converted to tf32)
        #pragma unroll
        for (int i = 0; i < 4; i++) {
            int idx = tid + i * 256;                 // 0..1023
            int r = idx >> 3, c4 = (idx & 7) * 4;
            float4 v = *reinterpret_cast<const float4*>(
                A + (size_t)(m0 + r) * DIM + kt + c4);
            *reinterpret_cast<uint4*>(&As[r][c4]) = f2tf4(v);
        }
        // stage W 32x128
        #pragma unroll
        for (int i = 0; i < 4; i++) {
            int idx = tid + i * 256;
            int r = idx >> 5, c4 = (idx & 31) * 4;
            float4 v = *reinterpret_cast<const float4*>(
                W + (size_t)(kt + r) * DIM + n0 + c4);
            *reinterpret_cast<uint4*>(&Ws[r][c4]) = f2tf4(v);
        }
        __syncthreads();

        #pragma unroll
        for (int ks = 0; ks < 4; ks++) {
            const int k8 = ks * 8;
            unsigned a[2][4];
            #pragma unroll
            for (int mt = 0; mt < 2; mt++) {
                int rb = wm * 32 + mt * 16;
                a[mt][0] = As[rb + g    ][k8 + tig];
                a[mt][1] = As[rb + g + 8][k8 + tig];
                a[mt][2] = As[rb + g    ][k8 + tig + 4];
                a[mt][3] = As[rb + g + 8][k8 + tig + 4];
            }
            #pragma unroll
            for (int nt = 0; nt < 8; nt++) {
                int cb = wn * 64 + nt * 8;
                unsigned b0 = Ws[k8 + tig    ][cb + g];
                unsigned b1 = Ws[k8 + tig + 4][cb + g];
                mma8(acc[0][nt], a[0], b0, b1);
                mma8(acc[1][nt], a[1], b0, b1);
            }
        }
        __syncthreads();
    }

    // epilogue
    #pragma unroll
    for (int mt = 0; mt < 2; mt++) {
        #pragma unroll
        for (int nt = 0; nt < 8; nt++) {
            int row = m0 + wm * 32 + mt * 16 + g;
            int col = n0 + wn * 64 + nt * 8 + 2 * tig;
            float v0 = acc[mt][nt][0], v1 = acc[mt][nt][1];
            float v2 = acc[mt][nt][2], v3 = acc[mt][nt][3];
            if (mode == 2) {
                float b0v = bias[col], b1v = bias[col + 1];
                *reinterpret_cast<float2*>(out + (size_t)row * DIM + col) =
                    make_float2(v0 + b0v, v1 + b1v);
                *reinterpret_cast<float2*>(out + (size_t)(row + 8) * DIM + col) =
                    make_float2(v2 + b0v, v3 + b1v);
            } else {
                if (mode == 1) {
                    float w0 = wK[row], w1 = wK[row + 8];
                    v0 *= w0; v1 *= w0; v2 *= w1; v3 *= w1;
                }
                size_t b = (size_t)(row >> 11);       // row / 2048
                size_t n = (size_t)(row & 2047);
                size_t h = (size_t)(col >> 6);
                size_t d = (size_t)(col & 63);
                size_t base = ((b * 16 + h) * 2048 + n) * 64 + d;
                *reinterpret_cast<float2*>(out + base) = make_float2(v0, v1);
                *reinterpret_cast<float2*>(out + base + 8 * 64) = make_float2(v2, v3);
            }
        }
    }
}

// ============================================================================
// Attention v4 (= v3 with Qs pitch fixed 36 -> 68):
// one CTA = one (b,h) x 128-query tile. 128 threads, 4 warps.
// Each warp owns 32 query rows (2 x m16) and the FULL 64-key / 64-dim width,
// so softmax P never crosses warps (warp-private smem scratch + __syncwarp).
// No-max softmax: O = (sum_k exp(s_k) v_k) / (sum_k exp(s_k)).
// K prefetched into regs before S-mma; V prefetched after sacc dies.
// Dynamic smem layout (words):
//   Qs[128][68]  : Q tile, tf32, 0.125 prescaled       (8704)
//   Ks[64][68]   : K tile [key][dim]                   (4352)
//   Vs[64][72]   : V tile [key][dim]                   (4608)
//   Ps[4][32][68]: per-warp P scratch [row][key]       (8704)
// total 26368 words = 103KB -> 2 CTAs/SM.
// ============================================================================
#define QS_OFF 0
#define KS_OFF 8704
#define VS_OFF (8704 + 4352)
#define PS_OFF (8704 + 4352 + 4608)
#define ATT_SMEM_BYTES ((8704 + 4352 + 4608 + 8704) * 4)

__global__ __launch_bounds__(128, 2) void attn_v4(
    const float* __restrict__ qbuf, const float* __restrict__ kbuf,
    const float* __restrict__ vbuf, float* __restrict__ attout)
{
    extern __shared__ unsigned smem[];
    unsigned* Qs = smem + QS_OFF;                    // [128][68]
    unsigned* Ks = smem + KS_OFF;                    // [64][68]
    unsigned* Vs = smem + VS_OFF;                    // [64][72]

    const int tid  = threadIdx.x;
    const int warp = tid >> 5, lane = tid & 31;
    const int g    = lane >> 2, tig = lane & 3;
    const int bh   = blockIdx.y;                     // 0..63
    const int q0   = blockIdx.x * 128;
    const int b    = bh >> 4, h = bh & 15;
    const size_t qbase  = ((size_t)bh * 2048 + q0) * 64;
    const size_t kvbase = (size_t)bh * 2048 * 64;
    const int rb = warp * 32;                        // warp's first query row
    unsigned* Pw = smem + PS_OFF + warp * (32 * 68); // warp-private P

    // ---- load Q tile 128x64 (scaled by 1/8, tf32): 2048 float4s ----
    #pragma unroll
    for (int i = 0; i < 16; i++) {
        int idx = tid + i * 128;                     // 0..2047
        int r = idx >> 4, c4 = (idx & 15) * 4;
        float4 v = *reinterpret_cast<const float4*>(
            qbuf + qbase + (size_t)r * 64 + c4);
        v.x *= 0.125f; v.y *= 0.125f; v.z *= 0.125f; v.w *= 0.125f;
        *reinterpret_cast<uint4*>(Qs + r * 68 + c4) = f2tf4(v);
    }
    // ---- stage first K/V tile: 64x64 = 1024 float4s each ----
    #pragma unroll
    for (int i = 0; i < 8; i++) {
        int idx = tid + i * 128;                     // 0..1023
        int r = idx >> 4, c4 = (idx & 15) * 4;
        float4 kv = *reinterpret_cast<const float4*>(kbuf + kvbase + (size_t)r * 64 + c4);
        *reinterpret_cast<uint4*>(Ks + r * 68 + c4) = f2tf4(kv);
        float4 vv = *reinterpret_cast<const float4*>(vbuf + kvbase + (size_t)r * 64 + c4);
        *reinterpret_cast<uint4*>(Vs + r * 72 + c4) = f2tf4(vv);
    }
    __syncthreads();

    float oacc[2][8][4];
    #pragma unroll
    for (int mt = 0; mt < 2; mt++)
        #pragma unroll
        for (int nt = 0; nt < 8; nt++)
            #pragma unroll
            for (int e = 0; e < 4; e++) oacc[mt][nt][e] = 0.f;
    float dsum[2][2] = {{0.f, 0.f}, {0.f, 0.f}};     // [mt][row-half]

    for (int kt = 0; kt < 32; kt++) {
        const bool pf = (kt < 31);
        const size_t src = kvbase + (size_t)(kt + 1) * 64 * 64;

        // ---- prefetch next K tile into registers (hidden under S-mma) ----
        float4 kp[8];
        if (pf) {
            #pragma unroll
            for (int i = 0; i < 8; i++) {
                int idx = tid + i * 128;
                int r = idx >> 4, c4 = (idx & 15) * 4;
                kp[i] = *reinterpret_cast<const float4*>(kbuf + src + (size_t)r * 64 + c4);
            }
        }

        // ---- S = Q K^T  (warp: 32 q-rows x 64 keys, k-dim 64) ----
        float sacc[2][8][4];
        #pragma unroll
        for (int mt = 0; mt < 2; mt++)
            #pragma unroll
            for (int nt = 0; nt < 8; nt++)
                #pragma unroll
                for (int e = 0; e < 4; e++) sacc[mt][nt][e] = 0.f;
        #pragma unroll
        for (int ks = 0; ks < 8; ks++) {
            const int k8 = ks * 8;
            unsigned aq[2][4];
            #pragma unroll
            for (int mt = 0; mt < 2; mt++) {
                const unsigned* qr = Qs + (rb + mt * 16 + g) * 68;
                aq[mt][0] = qr[k8 + tig];
                aq[mt][1] = qr[8 * 68 + k8 + tig];
                aq[mt][2] = qr[k8 + tig + 4];
                aq[mt][3] = qr[8 * 68 + k8 + tig + 4];
            }
            #pragma unroll
            for (int nt = 0; nt < 8; nt++) {
                const unsigned* kr = Ks + (nt * 8 + g) * 68;
                unsigned b0 = kr[k8 + tig];
                unsigned b1 = kr[k8 + tig + 4];
                mma8(sacc[0][nt], aq[0], b0, b1);
                mma8(sacc[1][nt], aq[1], b0, b1);
            }
        }

        // ---- P = exp(S) -> warp-private smem; accumulate denominator ----
        #pragma unroll
        for (int mt = 0; mt < 2; mt++) {
            #pragma unroll
            for (int nt = 0; nt < 8; nt++) {
                float e0 = __expf(sacc[mt][nt][0]);
                float e1 = __expf(sacc[mt][nt][1]);
                float e2 = __expf(sacc[mt][nt][2]);
                float e3 = __expf(sacc[mt][nt][3]);
                unsigned* pr = Pw + (mt * 16 + g) * 68 + nt * 8 + 2 * tig;
                pr[0]          = f2tf(e0);
                pr[1]          = f2tf(e1);
                pr[8 * 68]     = f2tf(e2);
                pr[8 * 68 + 1] = f2tf(e3);
                dsum[mt][0] += e0 + e1;
                dsum[mt][1] += e2 + e3;
            }
        }

        // ---- prefetch next V tile (sacc registers now dead) ----
        float4 vp[8];
        if (pf) {
            #pragma unroll
            for (int i = 0; i < 8; i++) {
                int idx = tid + i * 128;
                int r = idx >> 4, c4 = (idx & 15) * 4;
                vp[i] = *reinterpret_cast<const float4*>(vbuf + src + (size_t)r * 64 + c4);
            }
        }
        __syncwarp();   // P visible within warp

        // ---- O += P V  (warp: 32 q-rows x 64 dims, k-dim 64 keys) ----
        #pragma unroll
        for (int ks = 0; ks < 8; ks++) {
            const int k8 = ks * 8;
            unsigned ap[2][4];
            #pragma unroll
            for (int mt = 0; mt < 2; mt++) {
                const unsigned* pr = Pw + (mt * 16 + g) * 68;
                ap[mt][0] = pr[k8 + tig];
                ap[mt][1] = pr[8 * 68 + k8 + tig];
                ap[mt][2] = pr[k8 + tig + 4];
                ap[mt][3] = pr[8 * 68 + k8 + tig + 4];
            }
            #pragma unroll
            for (int nt = 0; nt < 8; nt++) {
                const unsigned* vr = Vs + (k8 + tig) * 72 + nt * 8 + g;
                unsigned b0 = vr[0];
                unsigned b1 = vr[4 * 72];
                mma8(oacc[0][nt], ap[0], b0, b1);
                mma8(oacc[1][nt], ap[1], b0, b1);
            }
        }

        // ---- commit prefetched tile ----
        if (pf) {
            __syncthreads();   // everyone done reading Ks/Vs
            #pragma unroll
            for (int i = 0; i < 8; i++) {
                int idx = tid + i * 128;
                int r = idx >> 4, c4 = (idx & 15) * 4;
                *reinterpret_cast<uint4*>(Ks + r * 68 + c4) = f2tf4(kp[i]);
                *reinterpret_cast<uint4*>(Vs + r * 72 + c4) = f2tf4(vp[i]);
            }
            __syncthreads();   // tile visible
        }
    }

    // ---- denominator: reduce across quad (cols) -> full row sums ----
    #pragma unroll
    for (int mt = 0; mt < 2; mt++) {
        #pragma unroll
        for (int rh = 0; rh < 2; rh++) {
            float d = dsum[mt][rh];
            d += __shfl_xor_sync(0xffffffffu, d, 1);
            d += __shfl_xor_sync(0xffffffffu, d, 2);
            dsum[mt][rh] = 1.f / d;
        }
    }

    // ---- write token-major attention output: att[b][q][h*64+d] ----
    #pragma unroll
    for (int mt = 0; mt < 2; mt++) {
        int row = q0 + rb + mt * 16 + g;
        float inv0 = dsum[mt][0], inv1 = dsum[mt][1];
        #pragma unroll
        for (int nt = 0; nt < 8; nt++) {
            int col = h * 64 + nt * 8 + 2 * tig;
            size_t base = ((size_t)b * 2048 + row) * 1024 + col;
            *reinterpret_cast<float2*>(attout + base) =
                make_float2(oacc[mt][nt][0] * inv0, oacc[mt][nt][1] * inv0);
            *reinterpret_cast<float2*>(attout + base + 8 * 1024) =
                make_float2(oacc[mt][nt][2] * inv1, oacc[mt][nt][3] * inv1);
        }
    }
}

// ============================================================================
extern "C" void kernel_launch(void* const* d_in, const int* in_sizes, int n_in,
                              void* d_out, int out_size) {
    (void)in_sizes; (void)n_in; (void)out_size;
    const float* Qtok = (const float*)d_in[0];
    const float* Ktok = (const float*)d_in[1];
    const float* Vtok = (const float*)d_in[2];
    const float* wK   = (const float*)d_in[3];
    const float* Wq   = (const float*)d_in[4];
    const float* Wk   = (const float*)d_in[5];
    const float* Wv   = (const float*)d_in[6];
    const float* Wo   = (const float*)d_in[7];
    const float* bo   = (const float*)d_in[8];
    float* out = (float*)d_out;

    float *qb, *kb, *vb, *ab;
    cudaGetSymbolAddress((void**)&qb, g_q);
    cudaGetSymbolAddress((void**)&kb, g_k);
    cudaGetSymbolAddress((void**)&vb, g_v);
    cudaGetSymbolAddress((void**)&ab, g_att);

    cudaFuncSetAttribute(attn_v4, cudaFuncAttributeMaxDynamicSharedMemorySize,
                         ATT_SMEM_BYTES);

    dim3 gg(DIM / 128, M_TOT / 128);   // (8, 64)
    gemm_tf32<<<gg, 256>>>(Qtok, Wq, qb, nullptr, nullptr, 0);
    gemm_tf32<<<gg, 256>>>(Ktok, Wk, kb, wK,      nullptr, 1);
    gemm_tf32<<<gg, 256>>>(Vtok, Wv, vb, nullptr, nullptr, 0);
    attn_v4<<<dim3(2048 / 128, 64), 128, ATT_SMEM_BYTES>>>(qb, kb, vb, ab);
    gemm_tf32<<<gg, 256>>>(ab, Wo, out, nullptr, bo, 2);
}